// round 1
// baseline (speedup 1.0000x reference)
#include <cuda_runtime.h>
#include <cuda_bf16.h>
#include <math.h>

// ---------------- problem constants ----------------
#define TT   100      // time steps after conv
#define BB   512      // batch
#define WW   18       // conv output width
#define CC   32       // conv channels
#define FF   576      // WW*CC lstm input features
#define HH   128      // hidden
#define GG   512      // 4*HH gates
#define NC   12       // classes

// ---------------- device scratch (no cudaMalloc allowed) ----------------
__device__ float g_seq [TT * BB * FF];   // (t,b,f)   ~118MB
__device__ float g_xp  [TT * BB * GG];   // (t,b,g)   ~105MB (reused: xp0, xp1, att tmp)
__device__ float g_h1  [TT * BB * HH];   // ~26MB
__device__ float g_h2  [TT * BB * HH];   // ~26MB
__device__ float g_whhT0[HH * GG];
__device__ float g_whhT1[HH * GG];
__device__ float g_wattT[HH * HH];
__device__ float g_attn [TT * BB];
__device__ float g_pooled[BB * HH];

__device__ __forceinline__ float sigf(float x) { return 1.0f / (1.0f + expf(-x)); }

// ---------------- conv + relu -> seq (t,b, w*32+c) ----------------
__global__ void __launch_bounds__(256) conv_kernel(const float* __restrict__ x,
                                                   const float* __restrict__ cw,
                                                   const float* __restrict__ cb) {
    int b = blockIdx.x;
    int t = blockIdx.y;
    __shared__ float patch[20 * 40];
    __shared__ float wts[32][101];
    __shared__ float bs[32];
    int tid = threadIdx.x;
    for (int l = tid; l < 800; l += 256) {
        int i = l / 40, j = l % 40;
        patch[l] = x[(b * 812 + t * 8 + i) * 40 + j];
    }
    for (int l = tid; l < 3200; l += 256) {
        wts[l / 100][l % 100] = cw[l];
    }
    if (tid < 32) bs[tid] = cb[tid];
    __syncthreads();
    for (int f = tid; f < FF; f += 256) {
        int c = f & 31, w = f >> 5;
        float acc = bs[c];
#pragma unroll
        for (int kh = 0; kh < 20; kh++)
#pragma unroll
            for (int kw = 0; kw < 5; kw++)
                acc += patch[kh * 40 + w * 2 + kw] * wts[c][kh * 5 + kw];
        g_seq[(t * BB + b) * FF + f] = fmaxf(acc, 0.0f);
    }
}

// ---------------- generic transpose: out[c*rows+r] = in[r*cols+c] ----------------
__global__ void transpose_kernel(const float* __restrict__ in, float* __restrict__ out,
                                 int rows, int cols) {
    int idx = blockIdx.x * 256 + threadIdx.x;
    if (idx < rows * cols) {
        int r = idx / cols, c = idx % cols;
        out[c * rows + r] = in[idx];
    }
}

// ---------------- fp32 SGEMM: C[M,N] = A[M,K] * B[N,K]^T + bias0 + bias1 ----------------
// M%128==0, N%64==0, K%16==0 (all shapes here satisfy this)
#define GBM 128
#define GBN 64
#define GBK 16
__global__ void __launch_bounds__(256) gemm_bias(const float* __restrict__ A,
                                                 const float* __restrict__ Bm,
                                                 const float* __restrict__ bias0,
                                                 const float* __restrict__ bias1,
                                                 float* __restrict__ C,
                                                 int M, int N, int K) {
    __shared__ float As[GBK][GBM + 4];
    __shared__ float Bs[GBK][GBN + 4];
    int tid = threadIdx.x;
    int tx = tid & 15, ty = tid >> 4;
    int bm = blockIdx.y * GBM, bn = blockIdx.x * GBN;
    float acc[8][4];
#pragma unroll
    for (int i = 0; i < 8; i++)
#pragma unroll
        for (int j = 0; j < 4; j++) acc[i][j] = 0.0f;

    for (int k0 = 0; k0 < K; k0 += GBK) {
#pragma unroll
        for (int i = 0; i < 8; i++) {
            int l = tid + i * 256;
            int r = l >> 4, c = l & 15;
            As[c][r] = A[(size_t)(bm + r) * K + k0 + c];
        }
#pragma unroll
        for (int i = 0; i < 4; i++) {
            int l = tid + i * 256;
            int r = l >> 4, c = l & 15;
            Bs[c][r] = Bm[(size_t)(bn + r) * K + k0 + c];
        }
        __syncthreads();
#pragma unroll
        for (int k = 0; k < GBK; k++) {
            float ra[8], rb[4];
#pragma unroll
            for (int i = 0; i < 8; i++) ra[i] = As[k][ty * 8 + i];
#pragma unroll
            for (int j = 0; j < 4; j++) rb[j] = Bs[k][tx * 4 + j];
#pragma unroll
            for (int i = 0; i < 8; i++)
#pragma unroll
                for (int j = 0; j < 4; j++) acc[i][j] += ra[i] * rb[j];
        }
        __syncthreads();
    }
#pragma unroll
    for (int i = 0; i < 8; i++) {
        int row = bm + ty * 8 + i;
#pragma unroll
        for (int j = 0; j < 4; j++) {
            int col = bn + tx * 4 + j;
            float v = acc[i][j];
            if (bias0) v += bias0[col];
            if (bias1) v += bias1[col];
            C[(size_t)row * N + col] = v;
        }
    }
}

// ---------------- LSTM recurrence: one CTA owns 4 batch rows for all T ----------------
// xp: (t,b,g) with biases pre-added. whhT[k*GG + r] = Whh[r*HH + k].
// smem weights: rows 0..255; rows 256..511 streamed from L2-resident whhT.
#define REC_SMEM (HH * 256 * 4 + 4 * HH * 4 * 2 + 4 * GG * 4)
__global__ void __launch_bounds__(256) lstm_rec(const float* __restrict__ xp,
                                                const float* __restrict__ whhT,
                                                float* __restrict__ hout) {
    extern __shared__ float sm[];
    float* w_s = sm;                         // [128][256]
    float* h_s = w_s + HH * 256;             // [4][128]
    float* c_s = h_s + 4 * HH;               // [4][128]
    float* g_s = c_s + 4 * HH;               // [4][512]
    int tid = threadIdx.x;
    int b0 = blockIdx.x * 4;

    for (int l = tid; l < HH * 256; l += 256) {
        int k = l >> 8, r = l & 255;
        w_s[l] = whhT[k * GG + r];
    }
    for (int l = tid; l < 4 * HH; l += 256) { h_s[l] = 0.0f; c_s[l] = 0.0f; }
    __syncthreads();

    const float* wg = whhT + 256 + tid;   // global rows 256..511, column tid

    for (int t = 0; t < TT; t++) {
        const float* xpt = xp + ((size_t)t * BB + b0) * GG;
        float acc0[4], acc1[4];
#pragma unroll
        for (int bb = 0; bb < 4; bb++) {
            acc0[bb] = xpt[bb * GG + tid];
            acc1[bb] = xpt[bb * GG + 256 + tid];
        }
#pragma unroll 8
        for (int k = 0; k < HH; k++) {
            float w0 = w_s[(k << 8) + tid];
            float w1 = __ldg(&wg[k * GG]);
#pragma unroll
            for (int bb = 0; bb < 4; bb++) {
                float hb = h_s[bb * HH + k];
                acc0[bb] += hb * w0;
                acc1[bb] += hb * w1;
            }
        }
#pragma unroll
        for (int bb = 0; bb < 4; bb++) {
            g_s[bb * GG + tid]       = acc0[bb];
            g_s[bb * GG + 256 + tid] = acc1[bb];
        }
        __syncthreads();
#pragma unroll
        for (int ii = 0; ii < 2; ii++) {
            int cidx = tid + ii * 256;           // = bb*128 + hh
            int bb = cidx >> 7, hh = cidx & 127;
            float gi = g_s[bb * GG + hh];
            float gf = g_s[bb * GG + 128 + hh];
            float gc = g_s[bb * GG + 256 + hh];
            float go = g_s[bb * GG + 384 + hh];
            float c  = sigf(gf) * c_s[cidx] + sigf(gi) * tanhf(gc);
            float h  = sigf(go) * tanhf(c);
            c_s[cidx] = c;
            h_s[cidx] = h;
            hout[((size_t)t * BB + b0 + bb) * HH + hh] = h;
        }
        __syncthreads();
    }
}

// ---------------- attn[n] = sum_h tanh(tmp[n,h]) * v[h], one warp per n ----------------
__global__ void __launch_bounds__(256) attn_kernel(const float* __restrict__ tmp,
                                                   const float* __restrict__ v) {
    int warp = threadIdx.x >> 5, lane = threadIdx.x & 31;
    int n = blockIdx.x * 8 + warp;
    const float* row = tmp + (size_t)n * HH;
    float s = 0.0f;
#pragma unroll
    for (int j = lane; j < HH; j += 32) s += tanhf(row[j]) * v[j];
#pragma unroll
    for (int o = 16; o; o >>= 1) s += __shfl_xor_sync(0xffffffffu, s, o);
    if (lane == 0) g_attn[n] = s;
}

// ---------------- softmax over T + weighted pool, one block per batch ----------------
__global__ void __launch_bounds__(128) pool_kernel() {
    int b = blockIdx.x;
    int tid = threadIdx.x;
    __shared__ float wt[TT];
    __shared__ float red[128];
    float a = (tid < TT) ? g_attn[tid * BB + b] : -1e30f;
    red[tid] = a;
    __syncthreads();
    for (int s = 64; s; s >>= 1) {
        if (tid < s) red[tid] = fmaxf(red[tid], red[tid + s]);
        __syncthreads();
    }
    float mx = red[0];
    __syncthreads();
    float e = (tid < TT) ? expf(a - mx) : 0.0f;
    red[tid] = e;
    __syncthreads();
    for (int s = 64; s; s >>= 1) {
        if (tid < s) red[tid] += red[tid + s];
        __syncthreads();
    }
    float inv = 1.0f / red[0];
    if (tid < TT) wt[tid] = e * inv;
    __syncthreads();
    float acc = 0.0f;
#pragma unroll 4
    for (int t = 0; t < TT; t++)
        acc += wt[t] * g_h2[((size_t)t * BB + b) * HH + tid];
    g_pooled[b * HH + tid] = acc;
}

// ---------------- head: out = (pooled@W1^T + b1)@W2^T + b2 ----------------
__global__ void __launch_bounds__(64) head_kernel(const float* __restrict__ W1,
                                                  const float* __restrict__ b1,
                                                  const float* __restrict__ W2,
                                                  const float* __restrict__ b2,
                                                  float* __restrict__ out) {
    int b = blockIdx.x;
    int tid = threadIdx.x;
    __shared__ float p[HH];
    __shared__ float hdn[64];
    for (int l = tid; l < HH; l += 64) p[l] = g_pooled[b * HH + l];
    __syncthreads();
    float acc = b1[tid];
#pragma unroll 8
    for (int k = 0; k < HH; k++) acc += p[k] * W1[tid * HH + k];
    hdn[tid] = acc;
    __syncthreads();
    if (tid < NC) {
        float o = b2[tid];
#pragma unroll
        for (int k = 0; k < 64; k++) o += hdn[k] * W2[tid * 64 + k];
        out[b * NC + tid] = o;
    }
}

// ---------------- host ----------------
extern "C" void kernel_launch(void* const* d_in, const int* in_sizes, int n_in,
                              void* d_out, int out_size) {
    const float* x      = (const float*)d_in[0];
    const float* conv_w = (const float*)d_in[1];
    const float* conv_b = (const float*)d_in[2];
    const float* Wih0   = (const float*)d_in[3];
    const float* Whh0   = (const float*)d_in[4];
    const float* bih0   = (const float*)d_in[5];
    const float* bhh0   = (const float*)d_in[6];
    const float* Wih1   = (const float*)d_in[7];
    const float* Whh1   = (const float*)d_in[8];
    const float* bih1   = (const float*)d_in[9];
    const float* bhh1   = (const float*)d_in[10];
    const float* W_att  = (const float*)d_in[11];
    const float* b_att  = (const float*)d_in[12];
    const float* v_att  = (const float*)d_in[13];
    const float* W1     = (const float*)d_in[14];
    const float* b1     = (const float*)d_in[15];
    const float* W2     = (const float*)d_in[16];
    const float* b2     = (const float*)d_in[17];
    float* out = (float*)d_out;

    float *seq_p, *xp_p, *h1_p, *h2_p, *whhT0_p, *whhT1_p, *wattT_p;
    cudaGetSymbolAddress((void**)&seq_p,   g_seq);
    cudaGetSymbolAddress((void**)&xp_p,    g_xp);
    cudaGetSymbolAddress((void**)&h1_p,    g_h1);
    cudaGetSymbolAddress((void**)&h2_p,    g_h2);
    cudaGetSymbolAddress((void**)&whhT0_p, g_whhT0);
    cudaGetSymbolAddress((void**)&whhT1_p, g_whhT1);
    cudaGetSymbolAddress((void**)&wattT_p, g_wattT);

    cudaFuncSetAttribute(lstm_rec, cudaFuncAttributeMaxDynamicSharedMemorySize, REC_SMEM);

    // weight transposes
    transpose_kernel<<<(GG * HH + 255) / 256, 256>>>(Whh0, whhT0_p, GG, HH);
    transpose_kernel<<<(GG * HH + 255) / 256, 256>>>(Whh1, whhT1_p, GG, HH);
    transpose_kernel<<<(HH * HH + 255) / 256, 256>>>(W_att, wattT_p, HH, HH);

    // conv -> seq
    conv_kernel<<<dim3(BB, TT), 256>>>(x, conv_w, conv_b);

    // x_proj layer 0: (51200,576) @ Wih0^T + bih0 + bhh0
    gemm_bias<<<dim3(GG / GBN, (TT * BB) / GBM), 256>>>(seq_p, Wih0, bih0, bhh0, xp_p,
                                                        TT * BB, GG, FF);
    // recurrence layer 0
    lstm_rec<<<BB / 4, 256, REC_SMEM>>>(xp_p, whhT0_p, h1_p);

    // x_proj layer 1: (51200,128) @ Wih1^T + bih1 + bhh1
    gemm_bias<<<dim3(GG / GBN, (TT * BB) / GBM), 256>>>(h1_p, Wih1, bih1, bhh1, xp_p,
                                                        TT * BB, GG, HH);
    // recurrence layer 1
    lstm_rec<<<BB / 4, 256, REC_SMEM>>>(xp_p, whhT1_p, h2_p);

    // attention pre-activation: (51200,128) @ W_att (not transposed -> use wattT) + b_att
    gemm_bias<<<dim3(HH / GBN, (TT * BB) / GBM), 256>>>(h2_p, wattT_p, b_att, nullptr,
                                                        xp_p, TT * BB, HH, HH);
    // attn scores
    attn_kernel<<<(TT * BB) / 8, 256>>>(xp_p, v_att);
    // softmax over T + pooling
    pool_kernel<<<BB, 128>>>();
    // head
    head_kernel<<<BB, 64>>>(W1, b1, W2, b2, out);
}